// round 1
// baseline (speedup 1.0000x reference)
#include <cuda_runtime.h>

#define T_STEPS 512
#define BATCH   256
#define NPTS    34
#define HID     512

// 256 MB hidden-state history [T][B][H] + cell state [B][H]
__device__ float g_hs[(size_t)T_STEPS * BATCH * HID];
__device__ float g_c[BATCH * HID];

__device__ __forceinline__ float sigm(float x) {
    return __fdividef(1.f, 1.f + __expf(-x));
}
__device__ __forceinline__ float tanh_fast(float x) {
    // 1 - 2/(e^{2x}+1); saturates correctly at +-inf
    return 1.f - __fdividef(2.f, __expf(2.f * x) + 1.f);
}

// One LSTM timestep: gates = points[t] @ W_ih^T + h_{t-1} @ W_hh^T + b, then cell update.
// Grid: (B/32, H/32) = (8, 16). Block: 256 threads = 8 warps.
// Warp w handles batch rows m0..m0+3 (m0 = 4w); lane handles hidden col n0+lane; 4 gates each.
__global__ __launch_bounds__(256) void lstm_step(
    const float* __restrict__ points,   // [T, B, 34]
    const float* __restrict__ W_ih,     // [2048, 34]
    const float* __restrict__ W_hh,     // [2048, 512]
    const float* __restrict__ b_ih,     // [2048]
    const float* __restrict__ b_hh,     // [2048]
    int t)
{
    __shared__ float As[32][35];        // h tile [m][k], pad 35 (broadcast reads)
    __shared__ float Bs[4][32][35];     // W tile [gate][n][k], pad 35 -> bank = (3n+k)%32, conflict-free

    const int tid  = threadIdx.x;
    const int lane = tid & 31;
    const int w    = tid >> 5;
    const int b0   = blockIdx.x * 32;
    const int n0   = blockIdx.y * 32;
    const int m0   = w * 4;

    float acc[4][4];
#pragma unroll
    for (int gg = 0; gg < 4; gg++)
#pragma unroll
        for (int m = 0; m < 4; m++) acc[gg][m] = 0.f;

    if (t > 0) {
        const float* hprev = g_hs + (size_t)(t - 1) * BATCH * HID;
        const int ar = tid >> 3, ac4 = tid & 7;   // A load: row, float4-col

        float4 pa, pb[4];
        // prologue: load chunk 0 into registers
        pa = *(const float4*)(hprev + (size_t)(b0 + ar) * HID + ac4 * 4);
#pragma unroll
        for (int i = 0; i < 4; i++) {
            int idx = tid + i * 256;                  // 0..1023 -> 1024 float4 of B tile
            int gg = idx >> 8, n = (idx >> 3) & 31, c4 = idx & 7;
            pb[i] = *(const float4*)(W_hh + (size_t)(gg * HID + n0 + n) * HID + c4 * 4);
        }

        for (int c = 0; c < 16; c++) {
            // commit prefetched chunk to smem
            As[ar][ac4 * 4 + 0] = pa.x; As[ar][ac4 * 4 + 1] = pa.y;
            As[ar][ac4 * 4 + 2] = pa.z; As[ar][ac4 * 4 + 3] = pa.w;
#pragma unroll
            for (int i = 0; i < 4; i++) {
                int idx = tid + i * 256;
                int gg = idx >> 8, n = (idx >> 3) & 31, c4 = idx & 7;
                Bs[gg][n][c4 * 4 + 0] = pb[i].x; Bs[gg][n][c4 * 4 + 1] = pb[i].y;
                Bs[gg][n][c4 * 4 + 2] = pb[i].z; Bs[gg][n][c4 * 4 + 3] = pb[i].w;
            }
            __syncthreads();

            // issue next chunk's global loads (overlap with compute)
            if (c < 15) {
                int k0 = (c + 1) * 32;
                pa = *(const float4*)(hprev + (size_t)(b0 + ar) * HID + k0 + ac4 * 4);
#pragma unroll
                for (int i = 0; i < 4; i++) {
                    int idx = tid + i * 256;
                    int gg = idx >> 8, n = (idx >> 3) & 31, c4 = idx & 7;
                    pb[i] = *(const float4*)(W_hh + (size_t)(gg * HID + n0 + n) * HID + k0 + c4 * 4);
                }
            }

#pragma unroll
            for (int k = 0; k < 32; k++) {
                float a0 = As[m0 + 0][k], a1 = As[m0 + 1][k];
                float a2 = As[m0 + 2][k], a3 = As[m0 + 3][k];
#pragma unroll
                for (int gg = 0; gg < 4; gg++) {
                    float bv = Bs[gg][lane][k];
                    acc[gg][0] += a0 * bv; acc[gg][1] += a1 * bv;
                    acc[gg][2] += a2 * bv; acc[gg][3] += a3 * bv;
                }
            }
            __syncthreads();
        }
    }

    // ---- input projection: K = 34 ----
    for (int idx = tid; idx < 32 * NPTS; idx += 256) {
        int r = idx / NPTS, k = idx - r * NPTS;
        As[r][k] = points[((size_t)t * BATCH + b0 + r) * NPTS + k];
    }
    for (int idx = tid; idx < 4 * 32 * NPTS; idx += 256) {
        int gg = idx / (32 * NPTS);
        int rem = idx - gg * (32 * NPTS);
        int n = rem / NPTS, k = rem - n * NPTS;
        Bs[gg][n][k] = W_ih[(size_t)(gg * HID + n0 + n) * NPTS + k];
    }
    __syncthreads();
#pragma unroll
    for (int k = 0; k < NPTS; k++) {
        float a0 = As[m0 + 0][k], a1 = As[m0 + 1][k];
        float a2 = As[m0 + 2][k], a3 = As[m0 + 3][k];
#pragma unroll
        for (int gg = 0; gg < 4; gg++) {
            float bv = Bs[gg][lane][k];
            acc[gg][0] += a0 * bv; acc[gg][1] += a1 * bv;
            acc[gg][2] += a2 * bv; acc[gg][3] += a3 * bv;
        }
    }

    // ---- LSTM cell epilogue ----
    const int n = n0 + lane;
    float bias[4];
#pragma unroll
    for (int gg = 0; gg < 4; gg++) bias[gg] = b_ih[gg * HID + n] + b_hh[gg * HID + n];

    float* hout = g_hs + (size_t)t * BATCH * HID;
#pragma unroll
    for (int m = 0; m < 4; m++) {
        int b = b0 + m0 + m;
        float iv = sigm(acc[0][m] + bias[0]);
        float fv = sigm(acc[1][m] + bias[1]);
        float gv = tanh_fast(acc[2][m] + bias[2]);
        float ov = sigm(acc[3][m] + bias[3]);
        float cp = (t > 0) ? g_c[(size_t)b * HID + n] : 0.f;
        float cn = fv * cp + iv * gv;
        g_c[(size_t)b * HID + n] = cn;
        hout[(size_t)b * HID + n] = ov * tanh_fast(cn);
    }
}

// Final: logits = hs @ W_lin^T + b_lin, softmax over 16.
// Block = 256 threads = 8 warps; each warp does 8 rows; grid = 131072/64 = 2048.
__global__ __launch_bounds__(256) void final_proj(
    const float* __restrict__ W_lin,   // [16, 512]
    const float* __restrict__ b_lin,   // [16]
    float* __restrict__ out)           // [131072, 16]
{
    __shared__ float Ws[16 * 512];
    __shared__ float bs[16];
    const int tid = threadIdx.x;
#pragma unroll
    for (int i = 0; i < 8; i++) {
        int idx4 = tid + i * 256;                 // 2048 float4 total
        ((float4*)Ws)[idx4] = ((const float4*)W_lin)[idx4];
    }
    if (tid < 16) bs[tid] = b_lin[tid];
    __syncthreads();

    const int lane = tid & 31, w = tid >> 5;
    for (int rr = 0; rr < 8; rr++) {
        size_t row = (size_t)blockIdx.x * 64 + w * 8 + rr;
        const float* hrow = g_hs + row * HID;
        float acc[16];
#pragma unroll
        for (int j = 0; j < 16; j++) acc[j] = 0.f;
#pragma unroll
        for (int kk = 0; kk < 16; kk++) {
            float hv = hrow[kk * 32 + lane];
#pragma unroll
            for (int j = 0; j < 16; j++)
                acc[j] += hv * Ws[j * 512 + kk * 32 + lane];
        }
#pragma unroll
        for (int j = 0; j < 16; j++) {
#pragma unroll
            for (int off = 16; off; off >>= 1)
                acc[j] += __shfl_xor_sync(0xffffffffu, acc[j], off);
        }
        float mx = -1e30f;
#pragma unroll
        for (int j = 0; j < 16; j++) { acc[j] += bs[j]; mx = fmaxf(mx, acc[j]); }
        float s = 0.f, e[16];
#pragma unroll
        for (int j = 0; j < 16; j++) { e[j] = __expf(acc[j] - mx); s += e[j]; }
        if (lane < 16) out[row * 16 + lane] = e[lane] / s;
    }
}

extern "C" void kernel_launch(void* const* d_in, const int* in_sizes, int n_in,
                              void* d_out, int out_size) {
    const float* points = (const float*)d_in[0];
    const float* W_ih   = (const float*)d_in[1];
    const float* W_hh   = (const float*)d_in[2];
    const float* b_ih   = (const float*)d_in[3];
    const float* b_hh   = (const float*)d_in[4];
    const float* W_lin  = (const float*)d_in[5];
    const float* b_lin  = (const float*)d_in[6];
    float* out = (float*)d_out;

    dim3 grid(BATCH / 32, HID / 32);   // (8, 16) = 128 CTAs
    for (int t = 0; t < T_STEPS; t++) {
        lstm_step<<<grid, 256>>>(points, W_ih, W_hh, b_ih, b_hh, t);
    }
    final_proj<<<(T_STEPS * BATCH) / 64, 256>>>(W_lin, b_lin, out);
}

// round 3
// speedup vs baseline: 1.5672x; 1.5672x over previous
#include <cuda_runtime.h>
#include <cuda_bf16.h>
#include <cstdint>

#define TT   512
#define BSZ  256
#define HID  512
#define NCTA 128

// ---- global scratch ----
__device__ __nv_bfloat16 g_h_hi[(size_t)TT * BSZ * HID];
__device__ __nv_bfloat16 g_h_lo[(size_t)TT * BSZ * HID];
__device__ __nv_bfloat16 g_x_hi[(size_t)TT * BSZ * 64];
__device__ __nv_bfloat16 g_x_lo[(size_t)TT * BSZ * 64];
__device__ unsigned g_epoch;   // zero-init; monotonic across replays
__device__ unsigned g_count;

// ---- smem layout (bytes from dynamic base) ----
// BHH: 32 rows x 512 bf16, row stride 1040B (260 b32, 260%32==4 -> conflict-free frags)
// BX : 32 rows x 64 bf16,  row stride 144B  (36 b32,  36%32==4)
// AS : 128 rows x 64 bf16, row stride 144B, 2 parts (hi/lo), double buffered
#define BHH(p)     ((p) * 33280)
#define BX(p)      (66560 + (p) * 4608)
#define AS(b, p)   (75776 + ((b) * 2 + (p)) * 18432)
#define RED        149504
#define SMEM_TOTAL 165888

__device__ __forceinline__ void mma16816(float* d, const uint32_t* a, const uint32_t* b) {
    asm volatile(
        "mma.sync.aligned.m16n8k16.row.col.f32.bf16.bf16.f32 "
        "{%0,%1,%2,%3}, {%4,%5,%6,%7}, {%8,%9}, {%0,%1,%2,%3};"
        : "+f"(d[0]), "+f"(d[1]), "+f"(d[2]), "+f"(d[3])
        : "r"(a[0]), "r"(a[1]), "r"(a[2]), "r"(a[3]), "r"(b[0]), "r"(b[1]));
}

__device__ __forceinline__ float sigm(float x) {
    return __fdividef(1.f, 1.f + __expf(-x));
}
__device__ __forceinline__ float tanh_fast(float x) {
    return 1.f - __fdividef(2.f, __expf(2.f * x) + 1.f);
}

__device__ __forceinline__ void grid_barrier() {
    __syncthreads();
    if (threadIdx.x == 0) {
        __threadfence();
        unsigned e = atomicAdd(&g_epoch, 0u);
        unsigned old = atomicAdd(&g_count, 1u);
        if (old == NCTA - 1) {
            g_count = 0u;
            __threadfence();
            atomicAdd(&g_epoch, 1u);
        } else {
            while (*(volatile unsigned*)&g_epoch == e) { }
            __threadfence();
        }
    }
    __syncthreads();
}

// ============================================================================
// Persistent LSTM: 128 CTAs x 256 threads.
// CTA (mh = bid&1, ng = bid>>1): batch rows mh*128..+128, h-cols n0=ng*8..+8.
// Gate-col j (0..31): gate = j>>3, hcol = n0 + (j&7).
// Warps: wm = warp&3 (32-row m block), wk = warp>>2 (K-split half).
// ============================================================================
__global__ void __launch_bounds__(256, 1) lstm_persist(
    const float* __restrict__ points, const float* __restrict__ W_ih,
    const float* __restrict__ W_hh, const float* __restrict__ b_ih,
    const float* __restrict__ b_hh)
{
    extern __shared__ char sm[];
    const int tid  = threadIdx.x;
    const int lane = tid & 31;
    const int warp = tid >> 5;
    const int wm = warp & 3, wk = warp >> 2;
    const int mh = blockIdx.x & 1;
    const int n0 = (blockIdx.x >> 1) * 8;

    // ---- prologue: W_hh slice -> smem (bf16 hi/lo, padded rows) ----
    for (int i = tid; i < 32 * 512; i += 256) {
        int j = i >> 9, k = i & 511;
        int wr = (j >> 3) * HID + n0 + (j & 7);
        float w = W_hh[(size_t)wr * HID + k];
        __nv_bfloat16 hi = __float2bfloat16(w);
        __nv_bfloat16 lo = __float2bfloat16(w - __bfloat162float(hi));
        *(__nv_bfloat16*)(sm + BHH(0) + j * 1040 + k * 2) = hi;
        *(__nv_bfloat16*)(sm + BHH(1) + j * 1040 + k * 2) = lo;
    }
    // ---- W_ih + fused bias (col 34), zero pad to 64 ----
    for (int i = tid; i < 32 * 64; i += 256) {
        int j = i >> 6, k = i & 63;
        int wr = (j >> 3) * HID + n0 + (j & 7);
        float v = (k < 34) ? W_ih[(size_t)wr * 34 + k]
                           : ((k == 34) ? (b_ih[wr] + b_hh[wr]) : 0.f);
        __nv_bfloat16 hi = __float2bfloat16(v);
        __nv_bfloat16 lo = __float2bfloat16(v - __bfloat162float(hi));
        *(__nv_bfloat16*)(sm + BX(0) + j * 144 + k * 2) = hi;
        *(__nv_bfloat16*)(sm + BX(1) + j * 144 + k * 2) = lo;
    }
    // ---- stage points as [T,B,64] bf16 hi/lo (col 34 = 1.0 bias lane) ----
    for (int i = tid; i < 65536; i += 256) {
        size_t e = (size_t)blockIdx.x * 65536 + i;
        int j = (int)(e & 63);
        size_t tb = e >> 6;
        float v = (j < 34) ? points[tb * 34 + j] : ((j == 34) ? 1.f : 0.f);
        __nv_bfloat16 hi = __float2bfloat16(v);
        g_x_hi[e] = hi;
        g_x_lo[e] = __float2bfloat16(v - __bfloat162float(hi));
    }
    grid_barrier();

    float cst[2][2][2];
#pragma unroll
    for (int a = 0; a < 2; a++)
#pragma unroll
        for (int b = 0; b < 2; b++)
#pragma unroll
            for (int c = 0; c < 2; c++) cst[a][b][c] = 0.f;

    float acc[2][4][4];
    uint4 rh4[4], rl4[4];

    for (int t = 0; t < TT; t++) {
        const int nch = t ? 9 : 1;
#pragma unroll
        for (int mt = 0; mt < 2; mt++)
#pragma unroll
            for (int nt = 0; nt < 4; nt++)
#pragma unroll
                for (int q = 0; q < 4; q++) acc[mt][nt][q] = 0.f;

        auto ldg_chunk = [&](int c) {
            bool isx = (t == 0) || (c == 8);
            if (isx) {
                const __nv_bfloat16* ph = g_x_hi + ((size_t)t * BSZ + mh * 128) * 64;
                const __nv_bfloat16* pl = g_x_lo + ((size_t)t * BSZ + mh * 128) * 64;
#pragma unroll
                for (int q = 0; q < 4; q++) {
                    int i = tid + q * 256, r = i >> 3, j8 = i & 7;
                    rh4[q] = *(const uint4*)(ph + r * 64 + j8 * 8);
                    rl4[q] = *(const uint4*)(pl + r * 64 + j8 * 8);
                }
            } else {
                const __nv_bfloat16* ph = g_h_hi + ((size_t)(t - 1) * BSZ + mh * 128) * HID + c * 64;
                const __nv_bfloat16* pl = g_h_lo + ((size_t)(t - 1) * BSZ + mh * 128) * HID + c * 64;
#pragma unroll
                for (int q = 0; q < 4; q++) {
                    int i = tid + q * 256, r = i >> 3, j8 = i & 7;
                    rh4[q] = *(const uint4*)(ph + (size_t)r * HID + j8 * 8);
                    rl4[q] = *(const uint4*)(pl + (size_t)r * HID + j8 * 8);
                }
            }
        };
        auto sts_chunk = [&](int buf) {
#pragma unroll
            for (int q = 0; q < 4; q++) {
                int i = tid + q * 256, r = i >> 3, j8 = i & 7;
                int off = r * 144 + j8 * 16;
                *(uint4*)(sm + AS(buf, 0) + off) = rh4[q];
                *(uint4*)(sm + AS(buf, 1) + off) = rl4[q];
            }
        };
        auto compute_chunk = [&](int buf, int bhb, int blb, int bstride) {
            const char* ahb = sm + AS(buf, 0);
            const char* alb = sm + AS(buf, 1);
#pragma unroll
            for (int kx = 0; kx < 2; kx++) {
                const int kb = (wk * 2 + kx) * 32 + (lane & 3) * 4;
                uint32_t ah[2][4], al[2][4];
#pragma unroll
                for (int mt = 0; mt < 2; mt++) {
                    int ro = (wm * 32 + mt * 16 + (lane >> 2)) * 144;
                    ah[mt][0] = *(const uint32_t*)(ahb + ro + kb);
                    ah[mt][1] = *(const uint32_t*)(ahb + ro + 8 * 144 + kb);
                    ah[mt][2] = *(const uint32_t*)(ahb + ro + kb + 16);
                    ah[mt][3] = *(const uint32_t*)(ahb + ro + 8 * 144 + kb + 16);
                    al[mt][0] = *(const uint32_t*)(alb + ro + kb);
                    al[mt][1] = *(const uint32_t*)(alb + ro + 8 * 144 + kb);
                    al[mt][2] = *(const uint32_t*)(alb + ro + kb + 16);
                    al[mt][3] = *(const uint32_t*)(alb + ro + 8 * 144 + kb + 16);
                }
                uint32_t bh[4][2], bl[4][2];
#pragma unroll
                for (int nt = 0; nt < 4; nt++) {
                    int ro = (nt * 8 + (lane >> 2)) * bstride + kb;
                    bh[nt][0] = *(const uint32_t*)(sm + bhb + ro);
                    bh[nt][1] = *(const uint32_t*)(sm + bhb + ro + 16);
                    bl[nt][0] = *(const uint32_t*)(sm + blb + ro);
                    bl[nt][1] = *(const uint32_t*)(sm + blb + ro + 16);
                }
#pragma unroll
                for (int mt = 0; mt < 2; mt++)
#pragma unroll
                    for (int nt = 0; nt < 4; nt++) {
                        mma16816(acc[mt][nt], ah[mt], bh[nt]);
                        mma16816(acc[mt][nt], ah[mt], bl[nt]);
                        mma16816(acc[mt][nt], al[mt], bh[nt]);
                    }
            }
        };

        ldg_chunk(0);
        sts_chunk(0);
        __syncthreads();

        for (int c = 0; c < nch; c++) {
            if (c + 1 < nch) ldg_chunk(c + 1);
            bool isx = (t == 0) || (c == 8);
            if (isx) compute_chunk(c & 1, BX(0), BX(1), 144);
            else     compute_chunk(c & 1, BHH(0) + c * 128, BHH(1) + c * 128, 1040);
            __syncthreads();
            if (c + 1 < nch) { sts_chunk((c + 1) & 1); __syncthreads(); }
        }

        // ---- K-split reduction ----
        if (wk == 1) {
            char* red = sm + RED + wm * 4096;
#pragma unroll
            for (int mt = 0; mt < 2; mt++)
#pragma unroll
                for (int nt = 0; nt < 4; nt++) {
                    int r0 = mt * 16 + (lane >> 2);
                    int cb = (nt * 8 + 2 * (lane & 3)) * 4;
                    *(float2*)(red + r0 * 128 + cb)       = make_float2(acc[mt][nt][0], acc[mt][nt][1]);
                    *(float2*)(red + (r0 + 8) * 128 + cb) = make_float2(acc[mt][nt][2], acc[mt][nt][3]);
                }
        }
        __syncthreads();

        if (wk == 0) {
            const char* red = sm + RED + wm * 4096;
#pragma unroll
            for (int mt = 0; mt < 2; mt++)
#pragma unroll
                for (int nt = 0; nt < 4; nt++) {
                    int r0 = mt * 16 + (lane >> 2);
                    int cb = (nt * 8 + 2 * (lane & 3)) * 4;
                    float2 v01 = *(const float2*)(red + r0 * 128 + cb);
                    float2 v23 = *(const float2*)(red + (r0 + 8) * 128 + cb);
                    acc[mt][nt][0] += v01.x; acc[mt][nt][1] += v01.y;
                    acc[mt][nt][2] += v23.x; acc[mt][nt][3] += v23.y;
                }

            // ---- cell update + h store (bias already folded via x col 34) ----
            size_t base_t = (size_t)t * BSZ * HID;
#pragma unroll
            for (int mt = 0; mt < 2; mt++)
#pragma unroll
                for (int rh = 0; rh < 2; rh++) {
                    int row_g = mh * 128 + wm * 32 + mt * 16 + (lane >> 2) + rh * 8;
                    uint32_t phh = 0, pll = 0;
#pragma unroll
                    for (int hc = 0; hc < 2; hc++) {
                        int q = rh * 2 + hc;
                        float iv = sigm(acc[mt][0][q]);
                        float fv = sigm(acc[mt][1][q]);
                        float gv = tanh_fast(acc[mt][2][q]);
                        float ov = sigm(acc[mt][3][q]);
                        float cn = fv * cst[mt][rh][hc] + iv * gv;
                        cst[mt][rh][hc] = cn;
                        float h = ov * tanh_fast(cn);
                        __nv_bfloat16 hi = __float2bfloat16(h);
                        __nv_bfloat16 lo = __float2bfloat16(h - __bfloat162float(hi));
                        unsigned short uhi = *(unsigned short*)&hi;
                        unsigned short ulo = *(unsigned short*)&lo;
                        phh |= (uint32_t)uhi << (hc * 16);
                        pll |= (uint32_t)ulo << (hc * 16);
                    }
                    size_t o = base_t + (size_t)row_g * HID + n0 + 2 * (lane & 3);
                    *(uint32_t*)(g_h_hi + o) = phh;
                    *(uint32_t*)(g_h_lo + o) = pll;
                }
        }
        grid_barrier();
    }
}

// ============================================================================
// Final projection + softmax, h = hi + lo.
// ============================================================================
__global__ void __launch_bounds__(256) final_proj(
    const float* __restrict__ W_lin, const float* __restrict__ b_lin,
    float* __restrict__ out)
{
    __shared__ float Ws[16 * 512];
    __shared__ float bs[16];
    const int tid = threadIdx.x;
#pragma unroll
    for (int i = 0; i < 8; i++)
        ((float4*)Ws)[tid + i * 256] = ((const float4*)W_lin)[tid + i * 256];
    if (tid < 16) bs[tid] = b_lin[tid];
    __syncthreads();

    const int lane = tid & 31, w = tid >> 5;
    for (int rr = 0; rr < 8; rr++) {
        size_t rowi = (size_t)blockIdx.x * 64 + w * 8 + rr;
        const __nv_bfloat16* hh = g_h_hi + rowi * HID;
        const __nv_bfloat16* hl = g_h_lo + rowi * HID;
        float acc[16];
#pragma unroll
        for (int j = 0; j < 16; j++) acc[j] = 0.f;
#pragma unroll
        for (int kk = 0; kk < 16; kk++) {
            int idx = kk * 32 + lane;
            float hv = __bfloat162float(hh[idx]) + __bfloat162float(hl[idx]);
#pragma unroll
            for (int j = 0; j < 16; j++)
                acc[j] += hv * Ws[j * 512 + idx];
        }
#pragma unroll
        for (int j = 0; j < 16; j++) {
#pragma unroll
            for (int off = 16; off; off >>= 1)
                acc[j] += __shfl_xor_sync(0xffffffffu, acc[j], off);
        }
        float mx = -1e30f;
#pragma unroll
        for (int j = 0; j < 16; j++) { acc[j] += bs[j]; mx = fmaxf(mx, acc[j]); }
        float s = 0.f, e[16];
#pragma unroll
        for (int j = 0; j < 16; j++) { e[j] = __expf(acc[j] - mx); s += e[j]; }
        if (lane < 16) out[rowi * 16 + lane] = e[lane] / s;
    }
}

extern "C" void kernel_launch(void* const* d_in, const int* in_sizes, int n_in,
                              void* d_out, int out_size) {
    const float* points = (const float*)d_in[0];
    const float* W_ih   = (const float*)d_in[1];
    const float* W_hh   = (const float*)d_in[2];
    const float* b_ih   = (const float*)d_in[3];
    const float* b_hh   = (const float*)d_in[4];
    const float* W_lin  = (const float*)d_in[5];
    const float* b_lin  = (const float*)d_in[6];
    float* out = (float*)d_out;

    cudaFuncSetAttribute(lstm_persist, cudaFuncAttributeMaxDynamicSharedMemorySize, SMEM_TOTAL);
    lstm_persist<<<NCTA, 256, SMEM_TOTAL>>>(points, W_ih, W_hh, b_ih, b_hh);
    final_proj<<<(TT * BSZ) / 64, 256>>>(W_lin, b_lin, out);
}

// round 6
// speedup vs baseline: 3.7860x; 2.4157x over previous
#include <cuda_runtime.h>
#include <cuda_fp16.h>
#include <cstdint>

#define TT   512
#define BSZ  256
#define HID  512
#define NCTA 128

// ---- global scratch ----
__device__ __half g_h[(size_t)TT * BSZ * HID];   // h history, fp16
__device__ __half g_x[(size_t)TT * BSZ * 64];    // points staged to 64-wide (col 34 = 1.0)
__device__ unsigned g_epoch;
__device__ unsigned g_count;

// ---- smem layout (bytes from dynamic base) ----
// BHH: 32 rows x 512 fp16, row stride 1040B (260 b32, 260%32==4 -> conflict-free)
// BX : 32 rows x 64 fp16,  row stride 144B  (36 b32, 36%32==4)
// AS : 128 rows x 64 fp16, row stride 144B, double buffered
#define BHH        0
#define BX         33280
#define AS(b)      (37888 + (b) * 18432)
#define SMEM_TOTAL 74752

__device__ __forceinline__ void mma16816(float* d, const uint32_t* a, const uint32_t* b) {
    asm volatile(
        "mma.sync.aligned.m16n8k16.row.col.f32.f16.f16.f32 "
        "{%0,%1,%2,%3}, {%4,%5,%6,%7}, {%8,%9}, {%0,%1,%2,%3};"
        : "+f"(d[0]), "+f"(d[1]), "+f"(d[2]), "+f"(d[3])
        : "r"(a[0]), "r"(a[1]), "r"(a[2]), "r"(a[3]), "r"(b[0]), "r"(b[1]));
}

__device__ __forceinline__ float sigm(float x) {
    return __fdividef(1.f, 1.f + __expf(-x));
}
__device__ __forceinline__ float tanh_fast(float x) {
    return 1.f - __fdividef(2.f, __expf(2.f * x) + 1.f);
}

__device__ __forceinline__ void grid_barrier() {
    __syncthreads();
    if (threadIdx.x == 0) {
        __threadfence();
        unsigned e = atomicAdd(&g_epoch, 0u);
        unsigned old = atomicAdd(&g_count, 1u);
        if (old == NCTA - 1) {
            g_count = 0u;
            __threadfence();
            atomicAdd(&g_epoch, 1u);
        } else {
            while (*(volatile unsigned*)&g_epoch == e) { }
            __threadfence();
        }
    }
    __syncthreads();
}

// ============================================================================
// Persistent LSTM: 128 CTAs x 256 threads, fp16 single-term MMA.
// CTA (mh = bid&1, ng = bid>>1): batch rows mh*128..+128, h-cols n0=ng*8..+8.
// Gate-col j (0..31): gate = j>>3, hcol = n0 + (j&7).
// Warp wm (0..7): rows wm*16..+16 (one m16 tile), N=32 (4 n8 tiles), full K.
// ============================================================================
__global__ void __launch_bounds__(256, 1) lstm_persist(
    const float* __restrict__ points, const float* __restrict__ W_ih,
    const float* __restrict__ W_hh, const float* __restrict__ b_ih,
    const float* __restrict__ b_hh)
{
    extern __shared__ char sm[];
    const int tid  = threadIdx.x;
    const int lane = tid & 31;
    const int wm   = tid >> 5;
    const int mh = blockIdx.x & 1;
    const int n0 = (blockIdx.x >> 1) * 8;

    // ---- prologue: W_hh slice -> smem fp16 ----
    for (int i = tid; i < 32 * 512; i += 256) {
        int j = i >> 9, k = i & 511;
        int wr = (j >> 3) * HID + n0 + (j & 7);
        *(__half*)(sm + BHH + j * 1040 + k * 2) = __float2half(W_hh[(size_t)wr * HID + k]);
    }
    // ---- W_ih + fused bias (col 34 multiplies the 1.0 lane), pad to 64 ----
    for (int i = tid; i < 32 * 64; i += 256) {
        int j = i >> 6, k = i & 63;
        int wr = (j >> 3) * HID + n0 + (j & 7);
        float v = (k < 34) ? W_ih[(size_t)wr * 34 + k]
                           : ((k == 34) ? (b_ih[wr] + b_hh[wr]) : 0.f);
        *(__half*)(sm + BX + j * 144 + k * 2) = __float2half(v);
    }
    // ---- stage points as [T,B,64] fp16 (col 34 = 1.0) ----
    for (int i = tid; i < 65536; i += 256) {
        size_t e = (size_t)blockIdx.x * 65536 + i;
        int j = (int)(e & 63);
        size_t tb = e >> 6;
        float v = (j < 34) ? points[tb * 34 + j] : ((j == 34) ? 1.f : 0.f);
        g_x[e] = __float2half(v);
    }
    grid_barrier();

    float cst[2][2];
#pragma unroll
    for (int a = 0; a < 2; a++)
#pragma unroll
        for (int b = 0; b < 2; b++) cst[a][b] = 0.f;

    float acc[4][4];
    uint4 rg[4];

    for (int t = 0; t < TT; t++) {
        const int nch = t ? 9 : 1;
#pragma unroll
        for (int nt = 0; nt < 4; nt++)
#pragma unroll
            for (int q = 0; q < 4; q++) acc[nt][q] = 0.f;

        auto ldg_chunk = [&](int c) {
            bool isx = (t == 0) || (c == 8);
            if (isx) {
                const __half* p = g_x + ((size_t)t * BSZ + mh * 128) * 64;
#pragma unroll
                for (int q = 0; q < 4; q++) {
                    int i = tid + q * 256, r = i >> 3, j8 = i & 7;
                    rg[q] = *(const uint4*)(p + r * 64 + j8 * 8);
                }
            } else {
                const __half* p = g_h + ((size_t)(t - 1) * BSZ + mh * 128) * HID + c * 64;
#pragma unroll
                for (int q = 0; q < 4; q++) {
                    int i = tid + q * 256, r = i >> 3, j8 = i & 7;
                    rg[q] = *(const uint4*)(p + (size_t)r * HID + j8 * 8);
                }
            }
        };
        auto sts_chunk = [&](int buf) {
#pragma unroll
            for (int q = 0; q < 4; q++) {
                int i = tid + q * 256, r = i >> 3, j8 = i & 7;
                *(uint4*)(sm + AS(buf) + r * 144 + j8 * 16) = rg[q];
            }
        };
        auto compute_chunk = [&](int buf, int bbase, int bstride) {
            const char* ab = sm + AS(buf);
#pragma unroll
            for (int ks = 0; ks < 4; ks++) {
                const int kb = ks * 32 + (lane & 3) * 4;
                const int ro = (wm * 16 + (lane >> 2)) * 144;
                uint32_t a[4];
                a[0] = *(const uint32_t*)(ab + ro + kb);
                a[1] = *(const uint32_t*)(ab + ro + 8 * 144 + kb);
                a[2] = *(const uint32_t*)(ab + ro + kb + 16);
                a[3] = *(const uint32_t*)(ab + ro + 8 * 144 + kb + 16);
#pragma unroll
                for (int nt = 0; nt < 4; nt++) {
                    uint32_t b[2];
                    int bo = bbase + (nt * 8 + (lane >> 2)) * bstride + kb;
                    b[0] = *(const uint32_t*)(sm + bo);
                    b[1] = *(const uint32_t*)(sm + bo + 16);
                    mma16816(acc[nt], a, b);
                }
            }
        };

        ldg_chunk(0);
        sts_chunk(0);
        __syncthreads();

        for (int c = 0; c < nch; c++) {
            if (c + 1 < nch) ldg_chunk(c + 1);
            bool isx = (t == 0) || (c == 8);
            if (isx) compute_chunk(c & 1, BX, 144);
            else     compute_chunk(c & 1, BHH + c * 128, 1040);
            if (c + 1 < nch) sts_chunk((c + 1) & 1);   // writes the other buffer
            __syncthreads();
        }

        // ---- cell update + h store ----
        size_t base_t = (size_t)t * BSZ * HID;
#pragma unroll
        for (int rh = 0; rh < 2; rh++) {
            int row_g = mh * 128 + wm * 16 + (lane >> 2) + rh * 8;
            uint32_t pk = 0;
#pragma unroll
            for (int hc = 0; hc < 2; hc++) {
                int q = rh * 2 + hc;
                float iv = sigm(acc[0][q]);
                float fv = sigm(acc[1][q]);
                float gv = tanh_fast(acc[2][q]);
                float ov = sigm(acc[3][q]);
                float cn = fv * cst[rh][hc] + iv * gv;
                cst[rh][hc] = cn;
                float h = ov * tanh_fast(cn);
                __half hv = __float2half(h);
                pk |= (uint32_t)(*(unsigned short*)&hv) << (hc * 16);
            }
            size_t o = base_t + (size_t)row_g * HID + n0 + 2 * (lane & 3);
            *(uint32_t*)(g_h + o) = pk;
        }
        grid_barrier();
    }
}

// ============================================================================
// Final projection + softmax (h in fp16).
// ============================================================================
__global__ void __launch_bounds__(256, 3) final_proj(
    const float* __restrict__ W_lin, const float* __restrict__ b_lin,
    float* __restrict__ out)
{
    __shared__ float Ws[16 * 512];
    __shared__ float bs[16];
    const int tid = threadIdx.x;
#pragma unroll
    for (int i = 0; i < 8; i++)
        ((float4*)Ws)[tid + i * 256] = ((const float4*)W_lin)[tid + i * 256];
    if (tid < 16) bs[tid] = b_lin[tid];
    __syncthreads();

    const int lane = tid & 31, w = tid >> 5;
    for (int rr = 0; rr < 8; rr++) {
        size_t rowi = (size_t)blockIdx.x * 64 + w * 8 + rr;
        const __half* hrow = g_h + rowi * HID;
        float acc[16];
#pragma unroll
        for (int j = 0; j < 16; j++) acc[j] = 0.f;
#pragma unroll 4
        for (int kk = 0; kk < 16; kk++) {
            int idx = kk * 32 + lane;
            float hv = __half2float(hrow[idx]);
#pragma unroll
            for (int j = 0; j < 16; j++)
                acc[j] += hv * Ws[j * 512 + idx];
        }
#pragma unroll
        for (int j = 0; j < 16; j++) {
#pragma unroll
            for (int off = 16; off; off >>= 1)
                acc[j] += __shfl_xor_sync(0xffffffffu, acc[j], off);
        }
        float mx = -1e30f;
#pragma unroll
        for (int j = 0; j < 16; j++) { acc[j] += bs[j]; mx = fmaxf(mx, acc[j]); }
        float s = 0.f;
#pragma unroll
        for (int j = 0; j < 16; j++) { acc[j] = __expf(acc[j] - mx); s += acc[j]; }
        if (lane < 16) out[rowi * 16 + lane] = acc[lane] / s;
    }
}

extern "C" void kernel_launch(void* const* d_in, const int* in_sizes, int n_in,
                              void* d_out, int out_size) {
    const float* points = (const float*)d_in[0];
    const float* W_ih   = (const float*)d_in[1];
    const float* W_hh   = (const float*)d_in[2];
    const float* b_ih   = (const float*)d_in[3];
    const float* b_hh   = (const float*)d_in[4];
    const float* W_lin  = (const float*)d_in[5];
    const float* b_lin  = (const float*)d_in[6];
    float* out = (float*)d_out;

    cudaFuncSetAttribute(lstm_persist, cudaFuncAttributeMaxDynamicSharedMemorySize, SMEM_TOTAL);
    lstm_persist<<<NCTA, 256, SMEM_TOTAL>>>(points, W_ih, W_hh, b_ih, b_hh);
    final_proj<<<(TT * BSZ) / 64, 256>>>(W_lin, b_lin, out);
}

// round 7
// speedup vs baseline: 4.3838x; 1.1579x over previous
#include <cuda_runtime.h>
#include <cuda_fp16.h>
#include <cstdint>

#define TT   512
#define BSZ  256
#define HID  512
#define NCTA 256
#define NTHR 128
#define GCTA 64

// ---- global scratch ----
__device__ __half g_h[(size_t)TT * BSZ * HID];   // h history, fp16
__device__ __half g_x[(size_t)TT * BSZ * 64];    // points staged 64-wide (col 34 = 1.0)
__device__ unsigned g_epoch[4], g_count[4];      // per-group barrier
__device__ unsigned g_epoch_all, g_count_all;    // one-time global barrier

// ---- smem layout (bytes from dynamic base) ----
// BHH: 32 rows x 512 fp16, stride 1040B (260 b32; 260%32==4 -> conflict-free)
// BX : 32 rows x 64 fp16,  stride 144B
// AS : 64 rows x 64 fp16,  stride 144B, double buffered
#define BHH        0
#define BX         33280
#define AS(b)      (37888 + (b) * 9216)
#define SMEM_TOTAL 56320

__device__ __forceinline__ void mma16816(float* d, const uint32_t* a, const uint32_t* b) {
    asm volatile(
        "mma.sync.aligned.m16n8k16.row.col.f32.f16.f16.f32 "
        "{%0,%1,%2,%3}, {%4,%5,%6,%7}, {%8,%9}, {%0,%1,%2,%3};"
        : "+f"(d[0]), "+f"(d[1]), "+f"(d[2]), "+f"(d[3])
        : "r"(a[0]), "r"(a[1]), "r"(a[2]), "r"(a[3]), "r"(b[0]), "r"(b[1]));
}

__device__ __forceinline__ float sigm(float x) {
    return __fdividef(1.f, 1.f + __expf(-x));
}
__device__ __forceinline__ float tanh_fast(float x) {
    return 1.f - __fdividef(2.f, __expf(2.f * x) + 1.f);
}

// ============================================================================
// Persistent LSTM: 256 CTAs x 128 threads (2 CTAs/SM).
// 4 independent batch groups of 64 rows; 64 CTAs per group.
// CTA (g = bid>>6, ng = bid&63): batch rows g*64..+64, h-cols n0=ng*8..+8.
// Gate-col j (0..31): gate = j>>3, hcol = n0 + (j&7).
// Warp wm (0..3): rows wm*16..+16 (one m16 tile), N=32 (4 n8 tiles), full K.
// Per step: x-chunk (no h dep) computed BEFORE the group-barrier wait.
// ============================================================================
__global__ void __launch_bounds__(NTHR, 2) lstm_persist(
    const float* __restrict__ points, const float* __restrict__ W_ih,
    const float* __restrict__ W_hh, const float* __restrict__ b_ih,
    const float* __restrict__ b_hh)
{
    extern __shared__ char sm[];
    const int tid  = threadIdx.x;
    const int lane = tid & 31;
    const int wm   = tid >> 5;
    const int bid  = blockIdx.x;
    const int g    = bid >> 6;
    const int ng   = bid & 63;
    const int n0   = ng * 8;
    const int bb   = g * 64;

    // ---- prologue: W_hh slice -> smem fp16 ----
    for (int i = tid; i < 32 * 512; i += NTHR) {
        int j = i >> 9, k = i & 511;
        int wr = (j >> 3) * HID + n0 + (j & 7);
        *(__half*)(sm + BHH + j * 1040 + k * 2) = __float2half(W_hh[(size_t)wr * HID + k]);
    }
    // ---- W_ih + fused bias (col 34 multiplies the 1.0 lane), pad to 64 ----
    for (int i = tid; i < 32 * 64; i += NTHR) {
        int j = i >> 6, k = i & 63;
        int wr = (j >> 3) * HID + n0 + (j & 7);
        float v = (k < 34) ? W_ih[(size_t)wr * 34 + k]
                           : ((k == 34) ? (b_ih[wr] + b_hh[wr]) : 0.f);
        *(__half*)(sm + BX + j * 144 + k * 2) = __float2half(v);
    }
    // ---- stage points as [T,B,64] fp16 (col 34 = 1.0) ----
    for (int i = tid; i < 32768; i += NTHR) {
        size_t e = (size_t)bid * 32768 + i;
        int j = (int)(e & 63);
        size_t tb = e >> 6;
        float v = (j < 34) ? points[tb * 34 + j] : ((j == 34) ? 1.f : 0.f);
        g_x[e] = __float2half(v);
    }

    // ---- one-time global barrier (g_x + smem W ready) ----
    __syncthreads();
    if (tid == 0) {
        __threadfence();
        unsigned e = *(volatile unsigned*)&g_epoch_all;
        if (atomicAdd(&g_count_all, 1u) == NCTA - 1) {
            *(volatile unsigned*)&g_count_all = 0u;
            __threadfence();
            atomicAdd(&g_epoch_all, 1u);
        } else {
            while (*(volatile unsigned*)&g_epoch_all == e) { }
        }
        __threadfence();
    }
    __syncthreads();

    float cst[2][2];
#pragma unroll
    for (int a = 0; a < 2; a++)
#pragma unroll
        for (int b = 0; b < 2; b++) cst[a][b] = 0.f;

    float acc[4][4];
    uint4 rg[4];
    unsigned ecap = 0;

    auto ldg_x = [&](int t) {
        const __half* p = g_x + ((size_t)t * BSZ + bb) * 64;
#pragma unroll
        for (int q = 0; q < 4; q++) {
            int i = tid + q * NTHR, r = i >> 3, j8 = i & 7;
            rg[q] = *(const uint4*)(p + r * 64 + j8 * 8);
        }
    };
    auto ldg_h = [&](int t, int c) {
        const __half* p = g_h + ((size_t)(t - 1) * BSZ + bb) * HID + c * 64;
#pragma unroll
        for (int q = 0; q < 4; q++) {
            int i = tid + q * NTHR, r = i >> 3, j8 = i & 7;
            rg[q] = *(const uint4*)(p + (size_t)r * HID + j8 * 8);
        }
    };
    auto sts_chunk = [&](int buf) {
#pragma unroll
        for (int q = 0; q < 4; q++) {
            int i = tid + q * NTHR, r = i >> 3, j8 = i & 7;
            *(uint4*)(sm + AS(buf) + r * 144 + j8 * 16) = rg[q];
        }
    };
    auto compute_chunk = [&](int buf, int bbase, int bstride) {
        const char* ab = sm + AS(buf);
#pragma unroll
        for (int ks = 0; ks < 4; ks++) {
            const int kb = ks * 32 + (lane & 3) * 4;
            const int ro = (wm * 16 + (lane >> 2)) * 144;
            uint32_t a[4];
            a[0] = *(const uint32_t*)(ab + ro + kb);
            a[1] = *(const uint32_t*)(ab + ro + 8 * 144 + kb);
            a[2] = *(const uint32_t*)(ab + ro + kb + 16);
            a[3] = *(const uint32_t*)(ab + ro + 8 * 144 + kb + 16);
#pragma unroll
            for (int nt = 0; nt < 4; nt++) {
                uint32_t b[2];
                int bo = bbase + (nt * 8 + (lane >> 2)) * bstride + kb;
                b[0] = *(const uint32_t*)(sm + bo);
                b[1] = *(const uint32_t*)(sm + bo + 16);
                mma16816(acc[nt], a, b);
            }
        }
    };

    for (int t = 0; t < TT; t++) {
#pragma unroll
        for (int nt = 0; nt < 4; nt++)
#pragma unroll
            for (int q = 0; q < 4; q++) acc[nt][q] = 0.f;

        // ---- x phase (no h dependency): hides the group-barrier wait ----
        ldg_x(t);
        sts_chunk(0);
        __syncthreads();
        compute_chunk(0, BX, 144);

        if (t > 0) {
            // ---- wait for group h_{t-1} completion (arrived at end of t-1) ----
            if (tid == 0) {
                while (*(volatile unsigned*)&g_epoch[g] == ecap) { }
                __threadfence();
            }
            __syncthreads();

            // ---- h chunks, double buffered (chunk c -> buf 1-(c&1)) ----
            ldg_h(t, 0);
            sts_chunk(1);
            __syncthreads();
            for (int c = 0; c < 8; c++) {
                if (c < 7) ldg_h(t, c + 1);
                compute_chunk(1 - (c & 1), BHH + c * 128, 1040);
                if (c < 7) sts_chunk(c & 1);
                __syncthreads();
            }
        }

        // ---- cell update + h store ----
        size_t base_t = (size_t)t * BSZ * HID;
#pragma unroll
        for (int rh = 0; rh < 2; rh++) {
            int row_g = bb + wm * 16 + (lane >> 2) + rh * 8;
            uint32_t pk = 0;
#pragma unroll
            for (int hc = 0; hc < 2; hc++) {
                int q = rh * 2 + hc;
                float iv = sigm(acc[0][q]);
                float fv = sigm(acc[1][q]);
                float gv = tanh_fast(acc[2][q]);
                float ov = sigm(acc[3][q]);
                float cn = fv * cst[rh][hc] + iv * gv;
                cst[rh][hc] = cn;
                float h = ov * tanh_fast(cn);
                __half hv = __float2half(h);
                pk |= (uint32_t)(*(unsigned short*)&hv) << (hc * 16);
            }
            size_t o = base_t + (size_t)row_g * HID + n0 + 2 * (lane & 3);
            *(uint32_t*)(g_h + o) = pk;
        }

        // ---- arrive at group barrier (wait happens next step, after x) ----
        __syncthreads();
        if (tid == 0) {
            __threadfence();
            ecap = *(volatile unsigned*)&g_epoch[g];
            if (atomicAdd(&g_count[g], 1u) == GCTA - 1) {
                *(volatile unsigned*)&g_count[g] = 0u;
                __threadfence();
                atomicAdd(&g_epoch[g], 1u);
            }
        }
    }
}

// ============================================================================
// Final projection + softmax (h in fp16).
// ============================================================================
__global__ void __launch_bounds__(256, 3) final_proj(
    const float* __restrict__ W_lin, const float* __restrict__ b_lin,
    float* __restrict__ out)
{
    __shared__ float Ws[16 * 512];
    __shared__ float bs[16];
    const int tid = threadIdx.x;
#pragma unroll
    for (int i = 0; i < 8; i++)
        ((float4*)Ws)[tid + i * 256] = ((const float4*)W_lin)[tid + i * 256];
    if (tid < 16) bs[tid] = b_lin[tid];
    __syncthreads();

    const int lane = tid & 31, w = tid >> 5;
    for (int rr = 0; rr < 8; rr++) {
        size_t rowi = (size_t)blockIdx.x * 64 + w * 8 + rr;
        const __half* hrow = g_h + rowi * HID;
        float acc[16];
#pragma unroll
        for (int j = 0; j < 16; j++) acc[j] = 0.f;
#pragma unroll 4
        for (int kk = 0; kk < 16; kk++) {
            int idx = kk * 32 + lane;
            float hv = __half2float(hrow[idx]);
#pragma unroll
            for (int j = 0; j < 16; j++)
                acc[j] += hv * Ws[j * 512 + idx];
        }
#pragma unroll
        for (int j = 0; j < 16; j++) {
#pragma unroll
            for (int off = 16; off; off >>= 1)
                acc[j] += __shfl_xor_sync(0xffffffffu, acc[j], off);
        }
        float mx = -1e30f;
#pragma unroll
        for (int j = 0; j < 16; j++) { acc[j] += bs[j]; mx = fmaxf(mx, acc[j]); }
        float s = 0.f;
#pragma unroll
        for (int j = 0; j < 16; j++) { acc[j] = __expf(acc[j] - mx); s += acc[j]; }
        if (lane < 16) out[rowi * 16 + lane] = acc[lane] / s;
    }
}

extern "C" void kernel_launch(void* const* d_in, const int* in_sizes, int n_in,
                              void* d_out, int out_size) {
    const float* points = (const float*)d_in[0];
    const float* W_ih   = (const float*)d_in[1];
    const float* W_hh   = (const float*)d_in[2];
    const float* b_ih   = (const float*)d_in[3];
    const float* b_hh   = (const float*)d_in[4];
    const float* W_lin  = (const float*)d_in[5];
    const float* b_lin  = (const float*)d_in[6];
    float* out = (float*)d_out;

    cudaFuncSetAttribute(lstm_persist, cudaFuncAttributeMaxDynamicSharedMemorySize, SMEM_TOTAL);
    lstm_persist<<<NCTA, NTHR, SMEM_TOTAL>>>(points, W_ih, W_hh, b_ih, b_hh);
    final_proj<<<(TT * BSZ) / 64, 256>>>(W_lin, b_lin, out);
}